// round 12
// baseline (speedup 1.0000x reference)
#include <cuda_runtime.h>
#include <math_constants.h>
#include <cstdint>

constexpr int B = 4, L = 2048, H = 8, D = 64, S = 2048;
constexpr int U = 40, NTOP = 40, BH = B * H;
constexpr int NSPLIT = 8;                // S split into 8 x 256 keys (4 tiles of 64)
constexpr int QCH = 20;                  // queries per chunk (2 chunks = 40)

__device__ float    g_M[BH * L];
__device__ int      g_top[BH * NTOP];
__device__ float    g_sumV[BH * D];
__device__ float    g_part[BH * 8 * D];
__device__ float    g_am[BH * NTOP * NSPLIT];
__device__ float    g_al[BH * NTOP * NSPLIT];
__device__ float    g_acc[BH * NTOP * NSPLIT * D];

// ---------------------------------------------------------------------------
__device__ __forceinline__ void cp_async16(void* smem, const void* gmem) {
    uint32_t s = (uint32_t)__cvta_generic_to_shared(smem);
    asm volatile("cp.async.cg.shared.global [%0], [%1], 16;\n" :: "r"(s), "l"(gmem));
}
#define CP_COMMIT() asm volatile("cp.async.commit_group;\n" ::: "memory")
#define CP_WAIT0()  asm volatile("cp.async.wait_group 0;\n" ::: "memory")

// ---- packed fp32x2 ops (Blackwell FFMA2 path) ------------------------------
typedef unsigned long long u64;
__device__ __forceinline__ u64 ffma2(u64 a, u64 b, u64 c) {
    u64 d; asm("fma.rn.f32x2 %0, %1, %2, %3;" : "=l"(d) : "l"(a), "l"(b), "l"(c));
    return d;
}
__device__ __forceinline__ u64 fadd2(u64 a, u64 b) {
    u64 d; asm("add.rn.f32x2 %0, %1, %2;" : "=l"(d) : "l"(a), "l"(b));
    return d;
}
__device__ __forceinline__ u64 pack2(float x) {
    u64 d; asm("mov.b64 %0, {%1, %1};" : "=l"(d) : "f"(x));
    return d;
}
__device__ __forceinline__ float2 unpack2(u64 a) {
    float lo, hi; asm("mov.b64 {%0, %1}, %2;" : "=f"(lo), "=f"(hi) : "l"(a));
    return make_float2(lo, hi);
}

// ---------------------------------------------------------------------------
// threefry2x32 (matches jax/_src/prng.py), partitionable path.
// ---------------------------------------------------------------------------
__device__ __forceinline__ uint2 threefry2x32(uint32_t k0, uint32_t k1,
                                              uint32_t x0, uint32_t x1) {
    uint32_t ks2 = k0 ^ k1 ^ 0x1BD11BDAu;
    x0 += k0; x1 += k1;
#define TF_RND(r) { x0 += x1; x1 = (x1 << (r)) | (x1 >> (32 - (r))); x1 ^= x0; }
    TF_RND(13) TF_RND(15) TF_RND(26) TF_RND(6)
    x0 += k1;  x1 += ks2 + 1u;
    TF_RND(17) TF_RND(29) TF_RND(16) TF_RND(24)
    x0 += ks2; x1 += k0 + 2u;
    TF_RND(13) TF_RND(15) TF_RND(26) TF_RND(6)
    x0 += k0;  x1 += k1 + 3u;
    TF_RND(17) TF_RND(29) TF_RND(16) TF_RND(24)
    x0 += k1;  x1 += ks2 + 4u;
    TF_RND(13) TF_RND(15) TF_RND(26) TF_RND(6)
    x0 += ks2; x1 += k0 + 5u;
#undef TF_RND
    return make_uint2(x0, x1);
}

// ---------------------------------------------------------------------------
// M: indices generated inline. 8-lane group per l-row, 32 rows/block.
// MLP=8 per group, 7-shuffle butterfly per 8 samples. grid = BH*L/32.
// ---------------------------------------------------------------------------
__global__ void __launch_bounds__(256, 5)
compute_M_kernel(const float* __restrict__ Q, const float* __restrict__ K) {
    int tid = threadIdx.x;
    int bh = blockIdx.x >> 6;
    int block_l = (blockIdx.x & 63) * 32;

    __shared__ int sidx[32 * U];
    {
        uint2 k2 = threefry2x32(0u, 42u, 0u, 1u);
        for (int i = tid; i < 32 * U; i += 256) {
            uint32_t gi = (uint32_t)(block_l * U + i);
            uint2 r = threefry2x32(k2.x, k2.y, 0u, gi);
            sidx[i] = (int)((r.x ^ r.y) & (uint32_t)(S - 1));
        }
    }
    __syncthreads();

    int warp = tid >> 5, lane = tid & 31;
    int g = lane >> 3, li = lane & 7;
    int r = warp * 4 + g;
    int l = block_l + r;
    const int* myidx = &sidx[r * U];

    const float4* Kb4 = (const float4*)(K + (size_t)bh * S * D);
    const float4* q4  = (const float4*)(Q + ((size_t)bh * L + l) * D);
    float4 qa = q4[li], qb = q4[li + 8];

    float mx = -CUDART_INF_F, sm = 0.f;
#pragma unroll
    for (int round = 0; round < 5; round++) {
        float p[8];
#pragma unroll
        for (int half = 0; half < 2; half++) {
            float4 ka[4], kb[4];
#pragma unroll
            for (int t = 0; t < 4; t++) {
                int kidx = myidx[round * 8 + half * 4 + t];
                ka[t] = Kb4[kidx * 16 + li];
                kb[t] = Kb4[kidx * 16 + 8 + li];
            }
#pragma unroll
            for (int t = 0; t < 4; t++) {
                p[half * 4 + t] =
                    qa.x * ka[t].x + qa.y * ka[t].y + qa.z * ka[t].z + qa.w * ka[t].w +
                    qb.x * kb[t].x + qb.y * kb[t].y + qb.z * kb[t].z + qb.w * kb[t].w;
            }
        }
#pragma unroll
        for (int o = 4; o; o >>= 1) {
#pragma unroll
            for (int j = 0; j < o; j++) {
                float a = p[j], b = p[j + o];
                float sel = (li & o) ? a : b;
                float got = __shfl_xor_sync(0xffffffffu, sel, o);
                p[j] = ((li & o) ? b : a) + got;
            }
        }
        mx = fmaxf(mx, p[0]);
        sm += p[0];
    }
#pragma unroll
    for (int o = 4; o; o >>= 1) {
        mx = fmaxf(mx, __shfl_xor_sync(0xffffffffu, mx, o));
        sm += __shfl_xor_sync(0xffffffffu, sm, o);
    }
    if (li == 0) g_M[bh * L + l] = mx - sm * (1.0f / (float)S);
}

// ---------------------------------------------------------------------------
// Exact top-40 per (bh) via 4-pass radix select (set semantics downstream).
// ---------------------------------------------------------------------------
__global__ void topk_kernel() {
    int bh = blockIdx.x, tid = threadIdx.x;
    int warp = tid >> 5;
    __shared__ uint32_t keys[L];
    __shared__ int hist[8][256];
    __shared__ int fin[256];
    __shared__ uint32_t sh_prefix;
    __shared__ int sh_need, sh_cnt;

    for (int i = tid; i < L; i += 256) {
        uint32_t b = __float_as_uint(g_M[bh * L + i]);
        keys[i] = (b & 0x80000000u) ? ~b : (b | 0x80000000u);
    }
    if (tid == 0) { sh_prefix = 0u; sh_need = NTOP; sh_cnt = 0; }
    __syncthreads();

    for (int shift = 24; shift >= 0; shift -= 8) {
        for (int i = tid; i < 8 * 256; i += 256) ((int*)hist)[i] = 0;
        __syncthreads();
        uint32_t prefix = sh_prefix;
        uint32_t maskhi = (shift == 24) ? 0u : (0xFFFFFFFFu << (shift + 8));
        for (int i = tid; i < L; i += 256) {
            uint32_t k = keys[i];
            if ((k & maskhi) == prefix)
                atomicAdd(&hist[warp][(k >> shift) & 255], 1);
        }
        __syncthreads();
        for (int i = tid; i < 256; i += 256) {
            int s = 0;
#pragma unroll
            for (int w = 0; w < 8; w++) s += hist[w][i];
            fin[i] = s;
        }
        __syncthreads();
        if (tid == 0) {
            int need = sh_need, cum = 0, d;
            for (d = 255; d >= 0; d--) {
                int c = fin[d];
                if (cum + c >= need) { sh_need = need - cum; break; }
                cum += c;
            }
            sh_prefix = prefix | ((uint32_t)d << shift);
        }
        __syncthreads();
    }
    uint32_t T = sh_prefix;
    int take_eq = sh_need;
    for (int i = tid; i < L; i += 256) {
        uint32_t k = keys[i];
        if (k > T) {
            int p = atomicAdd(&sh_cnt, 1);
            g_top[bh * NTOP + p] = i;
        } else if (k == T) {
            int r = 0;
            for (int j = 0; j < i; j++) if (keys[j] == T) r++;
            if (r < take_eq) {
                int p = atomicAdd(&sh_cnt, 1);
                g_top[bh * NTOP + p] = i;
            }
        }
    }
}

// ---------------------------------------------------------------------------
// sumV: float4 partials, deep MLP.
// ---------------------------------------------------------------------------
__global__ void sumv_part_kernel(const float* __restrict__ V) {
    int blk = blockIdx.x;
    int bh = blk >> 3, p = blk & 7;
    int tid = threadIdx.x;
    int d4 = tid & 15, r0 = tid >> 4;
    const float4* vb = (const float4*)(V + ((size_t)bh * S + (size_t)p * 256) * D);
    float4 a = make_float4(0.f, 0.f, 0.f, 0.f);
#pragma unroll
    for (int j = 0; j < 16; j++) {
        float4 v = vb[(size_t)(j * 16 + r0) * 16 + d4];
        a.x += v.x; a.y += v.y; a.z += v.z; a.w += v.w;
    }
    __shared__ float4 red[256];
    red[tid] = a;
    __syncthreads();
    for (int s = 128; s >= 16; s >>= 1) {
        if (tid < s) {
            red[tid].x += red[tid + s].x; red[tid].y += red[tid + s].y;
            red[tid].z += red[tid + s].z; red[tid].w += red[tid + s].w;
        }
        __syncthreads();
    }
    if (tid < 16) ((float4*)g_part)[(bh * 8 + p) * 16 + tid] = red[tid];
}

__global__ void sumv_reduce_kernel() {
    int bh = blockIdx.x, d = threadIdx.x;
    float s = 0.f;
#pragma unroll
    for (int p = 0; p < 8; p++) s += g_part[(bh * 8 + p) * D + d];
    g_sumV[bh * D + d] = s;
}

__global__ void fill_kernel(float4* __restrict__ out) {
    int i = blockIdx.x * blockDim.x + threadIdx.x;
    int d4 = i & 15;
    int bh = i >> 15;
    out[i] = ((const float4*)g_sumV)[bh * 16 + d4];
}

// ---------------------------------------------------------------------------
// Attention partials, no max-subtraction, packed f32x2 FMA (FFMA2) in both
// GEMM loops. cp.async pipeline: V_t during QK_t; K_{t+1} during PV_t.
// ---------------------------------------------------------------------------
__global__ void __launch_bounds__(160, 5) attn_kernel(const float* __restrict__ Q,
                                                      const float* __restrict__ K,
                                                      const float* __restrict__ V) {
    int bid = blockIdx.x;
    int split = bid & (NSPLIT - 1);
    int chunk = (bid >> 3) & 1;
    int bh = bid >> 4;
    int tid = threadIdx.x, w = tid >> 5, lane = tid & 31;

    __shared__ float4 Kb[64][17];
    __shared__ float4 Vb[64][17];
    __shared__ __align__(16) float Qs[QCH][64];
    __shared__ float4 Ps[5][64];

    const float4* Kb4 = (const float4*)(K + (size_t)bh * S * D);
    const float4* Vb4 = (const float4*)(V + (size_t)bh * S * D);

    // prefetch K tile 0
    {
        int kbase = split * 256;
        for (int i = tid; i < 1024; i += 160) {
            int s = i >> 4, c = i & 15;
            cp_async16(&Kb[s][c], &Kb4[(size_t)(kbase + s) * 16 + c]);
        }
        CP_COMMIT();
    }
    for (int i = tid; i < QCH * 64; i += 160) {
        int q = i >> 6, d = i & 63;
        int qrow = g_top[bh * NTOP + chunk * QCH + q];
        Qs[q][d] = Q[((size_t)bh * L + qrow) * D + d];
    }

    int sg = lane >> 3, dg = lane & 7;
    float lsum[4] = {0.f, 0.f, 0.f, 0.f};
    // packed accumulators: [qq][0..3] = dim-pairs (dg*4+0,1)(dg*4+2,3)((dg+8)*4+0,1)((dg+8)*4+2,3)
    u64 accp[4][4];
#pragma unroll
    for (int qq = 0; qq < 4; qq++)
#pragma unroll
        for (int j = 0; j < 4; j++) accp[qq][j] = 0ull;

#pragma unroll
    for (int t = 0; t < 4; t++) {
        int kbase = split * 256 + t * 64;
        CP_WAIT0();
        __syncthreads();                      // K_t ready; Vb/Ps free

        // prefetch V_t (overlaps with QK)
        for (int i = tid; i < 1024; i += 160) {
            int s = i >> 4, c = i & 15;
            cp_async16(&Vb[s][c], &Vb4[(size_t)(kbase + s) * 16 + c]);
        }
        CP_COMMIT();

        // QK: packed pairwise dots; keys (lane, lane+32) for 4 queries
        u64 s0p[4] = {0ull, 0ull, 0ull, 0ull}, s1p[4] = {0ull, 0ull, 0ull, 0ull};
#pragma unroll
        for (int d4 = 0; d4 < 16; d4++) {
            ulonglong2 k0 = *(const ulonglong2*)&Kb[lane][d4];
            ulonglong2 k1 = *(const ulonglong2*)&Kb[lane + 32][d4];
#pragma unroll
            for (int qq = 0; qq < 4; qq++) {
                ulonglong2 a = *(const ulonglong2*)&Qs[4 * w + qq][d4 * 4];
                s0p[qq] = ffma2(a.x, k0.x, s0p[qq]);
                s0p[qq] = ffma2(a.y, k0.y, s0p[qq]);
                s1p[qq] = ffma2(a.x, k1.x, s1p[qq]);
                s1p[qq] = ffma2(a.y, k1.y, s1p[qq]);
            }
        }
        float pv0[4], pv1[4];
#pragma unroll
        for (int qq = 0; qq < 4; qq++) {
            float2 t0 = unpack2(s0p[qq]);
            float2 t1 = unpack2(s1p[qq]);
            pv0[qq] = __expf((t0.x + t0.y) * 0.125f);
            pv1[qq] = __expf((t1.x + t1.y) * 0.125f);
            lsum[qq] += pv0[qq] + pv1[qq];
        }
        Ps[w][lane]      = make_float4(pv0[0], pv0[1], pv0[2], pv0[3]);
        Ps[w][lane + 32] = make_float4(pv1[0], pv1[1], pv1[2], pv1[3]);

        CP_WAIT0();
        __syncthreads();                      // V_t ready; done reading Kb

        // prefetch K_{t+1} (overlaps with PV)
        if (t < 3) {
            int nbase = kbase + 64;
            for (int i = tid; i < 1024; i += 160) {
                int s = i >> 4, c = i & 15;
                cp_async16(&Kb[s][c], &Kb4[(size_t)(nbase + s) * 16 + c]);
            }
            CP_COMMIT();
        }

        // PV: thread handles keys [sg*16,+16), dims [dg*4,+4) & [(dg+8)*4,+4)
#pragma unroll
        for (int i = 0; i < 16; i++) {
            int s = sg * 16 + i;
            float4 p  = Ps[w][s];
            ulonglong2 va = *(const ulonglong2*)&Vb[s][dg];
            ulonglong2 vb = *(const ulonglong2*)&Vb[s][dg + 8];
            u64 p2[4] = {pack2(p.x), pack2(p.y), pack2(p.z), pack2(p.w)};
#pragma unroll
            for (int qq = 0; qq < 4; qq++) {
                accp[qq][0] = ffma2(p2[qq], va.x, accp[qq][0]);
                accp[qq][1] = ffma2(p2[qq], va.y, accp[qq][1]);
                accp[qq][2] = ffma2(p2[qq], vb.x, accp[qq][2]);
                accp[qq][3] = ffma2(p2[qq], vb.y, accp[qq][3]);
            }
        }
    }

    // one-time reductions: lsum over 32 lanes; acc over the 4 sgroups
#pragma unroll
    for (int qq = 0; qq < 4; qq++) {
#pragma unroll
        for (int o = 16; o; o >>= 1)
            lsum[qq] += __shfl_xor_sync(0xffffffffu, lsum[qq], o);
#pragma unroll
        for (int j = 0; j < 4; j++) {
#pragma unroll
            for (int o = 8; o <= 16; o <<= 1) {
                u64 got = __shfl_xor_sync(0xffffffffu, accp[qq][j], o);
                accp[qq][j] = fadd2(accp[qq][j], got);
            }
        }
    }

    if (lane < 8) {
#pragma unroll
        for (int qq = 0; qq < 4; qq++) {
            int pa = (bh * NTOP + chunk * QCH + 4 * w + qq) * NSPLIT + split;
            ((ulonglong2*)g_acc)[pa * 16 + dg]     = make_ulonglong2(accp[qq][0], accp[qq][1]);
            ((ulonglong2*)g_acc)[pa * 16 + 8 + dg] = make_ulonglong2(accp[qq][2], accp[qq][3]);
        }
    }
    if (lane == 0) {
#pragma unroll
        for (int qq = 0; qq < 4; qq++) {
            int pa = (bh * NTOP + chunk * QCH + 4 * w + qq) * NSPLIT + split;
            g_am[pa] = 0.f; g_al[pa] = lsum[qq];
        }
    }
}

// ---------------------------------------------------------------------------
// Merge the 8 split partials per (bh, q) and write the output row.
// ---------------------------------------------------------------------------
__global__ void merge_kernel(float* __restrict__ out) {
    int w = (blockIdx.x * blockDim.x + threadIdx.x) >> 5;
    int lane = threadIdx.x & 31;
    if (w >= BH * NTOP) return;
    int bh = w / NTOP, qi = w % NTOP;
    int base = w * NSPLIT;

    float Lsum = 0.f, o0 = 0.f, o1 = 0.f;
#pragma unroll
    for (int s = 0; s < NSPLIT; s++) {
        Lsum += g_al[base + s];
        o0 += g_acc[(base + s) * D + lane];
        o1 += g_acc[(base + s) * D + lane + 32];
    }
    int row = g_top[bh * NTOP + qi];
    size_t orow = ((size_t)bh * L + row) * D;
    float inv = 1.0f / Lsum;
    out[orow + lane]      = o0 * inv;
    out[orow + lane + 32] = o1 * inv;
}

// ---------------------------------------------------------------------------
extern "C" void kernel_launch(void* const* d_in, const int* in_sizes, int n_in,
                              void* d_out, int out_size) {
    const float* q = (const float*)d_in[0];
    const float* k = (const float*)d_in[1];
    const float* v = (const float*)d_in[2];
    float* out = (float*)d_out;

    compute_M_kernel<<<BH * (L / 32), 256>>>(q, k);                 // 1
    topk_kernel<<<BH, 256>>>();                                     // 2
    sumv_part_kernel<<<BH * 8, 256>>>(v);                           // 3
    attn_kernel<<<BH * 2 * NSPLIT, 160>>>(q, k, v);                 // 4 <- profiled
    sumv_reduce_kernel<<<BH, 64>>>();                               // 5
    fill_kernel<<<(B * H * L * D / 4) / 256, 256>>>((float4*)out);  // 6
    merge_kernel<<<(BH * NTOP * 32 + 255) / 256, 256>>>(out);       // 7
}

// round 13
// speedup vs baseline: 1.0525x; 1.0525x over previous
#include <cuda_runtime.h>
#include <math_constants.h>
#include <cstdint>

constexpr int B = 4, L = 2048, H = 8, D = 64, S = 2048;
constexpr int U = 40, NTOP = 40, BH = B * H;
constexpr int NSPLIT = 8;                // S split into 8 x 256 keys (4 tiles of 64)
constexpr int QCH = 20;                  // queries per chunk (2 chunks = 40)

__device__ float    g_M[BH * L];
__device__ int      g_top[BH * NTOP];
__device__ float    g_part[BH * 8 * D];
__device__ float    g_am[BH * NTOP * NSPLIT];
__device__ float    g_al[BH * NTOP * NSPLIT];
__device__ float    g_acc[BH * NTOP * NSPLIT * D];

// ---------------------------------------------------------------------------
__device__ __forceinline__ void cp_async16(void* smem, const void* gmem) {
    uint32_t s = (uint32_t)__cvta_generic_to_shared(smem);
    asm volatile("cp.async.cg.shared.global [%0], [%1], 16;\n" :: "r"(s), "l"(gmem));
}
#define CP_COMMIT() asm volatile("cp.async.commit_group;\n" ::: "memory")
#define CP_WAIT0()  asm volatile("cp.async.wait_group 0;\n" ::: "memory")

// ---- packed fp32x2 ops (Blackwell FFMA2 path) ------------------------------
typedef unsigned long long u64;
__device__ __forceinline__ u64 ffma2(u64 a, u64 b, u64 c) {
    u64 d; asm("fma.rn.f32x2 %0, %1, %2, %3;" : "=l"(d) : "l"(a), "l"(b), "l"(c));
    return d;
}
__device__ __forceinline__ u64 fadd2(u64 a, u64 b) {
    u64 d; asm("add.rn.f32x2 %0, %1, %2;" : "=l"(d) : "l"(a), "l"(b));
    return d;
}
__device__ __forceinline__ u64 pack2(float x) {
    u64 d; asm("mov.b64 %0, {%1, %1};" : "=l"(d) : "f"(x));
    return d;
}
__device__ __forceinline__ float2 unpack2(u64 a) {
    float lo, hi; asm("mov.b64 {%0, %1}, %2;" : "=f"(lo), "=f"(hi) : "l"(a));
    return make_float2(lo, hi);
}

// ---------------------------------------------------------------------------
// threefry2x32 (matches jax/_src/prng.py), partitionable path.
// ---------------------------------------------------------------------------
__device__ __forceinline__ uint2 threefry2x32(uint32_t k0, uint32_t k1,
                                              uint32_t x0, uint32_t x1) {
    uint32_t ks2 = k0 ^ k1 ^ 0x1BD11BDAu;
    x0 += k0; x1 += k1;
#define TF_RND(r) { x0 += x1; x1 = (x1 << (r)) | (x1 >> (32 - (r))); x1 ^= x0; }
    TF_RND(13) TF_RND(15) TF_RND(26) TF_RND(6)
    x0 += k1;  x1 += ks2 + 1u;
    TF_RND(17) TF_RND(29) TF_RND(16) TF_RND(24)
    x0 += ks2; x1 += k0 + 2u;
    TF_RND(13) TF_RND(15) TF_RND(26) TF_RND(6)
    x0 += k0;  x1 += k1 + 3u;
    TF_RND(17) TF_RND(29) TF_RND(16) TF_RND(24)
    x0 += k1;  x1 += ks2 + 4u;
    TF_RND(13) TF_RND(15) TF_RND(26) TF_RND(6)
    x0 += ks2; x1 += k0 + 5u;
#undef TF_RND
    return make_uint2(x0, x1);
}

// ---------------------------------------------------------------------------
// M: indices generated inline. 8-lane group per l-row, 32 rows/block.
// MLP=8 per group, 7-shuffle butterfly per 8 samples. grid = BH*L/32.
// ---------------------------------------------------------------------------
__global__ void __launch_bounds__(256, 5)
compute_M_kernel(const float* __restrict__ Q, const float* __restrict__ K) {
    int tid = threadIdx.x;
    int bh = blockIdx.x >> 6;
    int block_l = (blockIdx.x & 63) * 32;

    __shared__ int sidx[32 * U];
    {
        uint2 k2 = threefry2x32(0u, 42u, 0u, 1u);
        for (int i = tid; i < 32 * U; i += 256) {
            uint32_t gi = (uint32_t)(block_l * U + i);
            uint2 r = threefry2x32(k2.x, k2.y, 0u, gi);
            sidx[i] = (int)((r.x ^ r.y) & (uint32_t)(S - 1));
        }
    }
    __syncthreads();

    int warp = tid >> 5, lane = tid & 31;
    int g = lane >> 3, li = lane & 7;
    int r = warp * 4 + g;
    int l = block_l + r;
    const int* myidx = &sidx[r * U];

    const float4* Kb4 = (const float4*)(K + (size_t)bh * S * D);
    const float4* q4  = (const float4*)(Q + ((size_t)bh * L + l) * D);
    float4 qa = q4[li], qb = q4[li + 8];

    float mx = -CUDART_INF_F, sm = 0.f;
#pragma unroll
    for (int round = 0; round < 5; round++) {
        float p[8];
#pragma unroll
        for (int half = 0; half < 2; half++) {
            float4 ka[4], kb[4];
#pragma unroll
            for (int t = 0; t < 4; t++) {
                int kidx = myidx[round * 8 + half * 4 + t];
                ka[t] = Kb4[kidx * 16 + li];
                kb[t] = Kb4[kidx * 16 + 8 + li];
            }
#pragma unroll
            for (int t = 0; t < 4; t++) {
                p[half * 4 + t] =
                    qa.x * ka[t].x + qa.y * ka[t].y + qa.z * ka[t].z + qa.w * ka[t].w +
                    qb.x * kb[t].x + qb.y * kb[t].y + qb.z * kb[t].z + qb.w * kb[t].w;
            }
        }
#pragma unroll
        for (int o = 4; o; o >>= 1) {
#pragma unroll
            for (int j = 0; j < o; j++) {
                float a = p[j], b = p[j + o];
                float sel = (li & o) ? a : b;
                float got = __shfl_xor_sync(0xffffffffu, sel, o);
                p[j] = ((li & o) ? b : a) + got;
            }
        }
        mx = fmaxf(mx, p[0]);
        sm += p[0];
    }
#pragma unroll
    for (int o = 4; o; o >>= 1) {
        mx = fmaxf(mx, __shfl_xor_sync(0xffffffffu, mx, o));
        sm += __shfl_xor_sync(0xffffffffu, sm, o);
    }
    if (li == 0) g_M[bh * L + l] = mx - sm * (1.0f / (float)S);
}

// ---------------------------------------------------------------------------
// Exact top-40 per (bh) via 4-pass radix select (set semantics downstream).
// ---------------------------------------------------------------------------
__global__ void topk_kernel() {
    int bh = blockIdx.x, tid = threadIdx.x;
    int warp = tid >> 5;
    __shared__ uint32_t keys[L];
    __shared__ int hist[8][256];
    __shared__ int fin[256];
    __shared__ uint32_t sh_prefix;
    __shared__ int sh_need, sh_cnt;

    for (int i = tid; i < L; i += 256) {
        uint32_t b = __float_as_uint(g_M[bh * L + i]);
        keys[i] = (b & 0x80000000u) ? ~b : (b | 0x80000000u);
    }
    if (tid == 0) { sh_prefix = 0u; sh_need = NTOP; sh_cnt = 0; }
    __syncthreads();

    for (int shift = 24; shift >= 0; shift -= 8) {
        for (int i = tid; i < 8 * 256; i += 256) ((int*)hist)[i] = 0;
        __syncthreads();
        uint32_t prefix = sh_prefix;
        uint32_t maskhi = (shift == 24) ? 0u : (0xFFFFFFFFu << (shift + 8));
        for (int i = tid; i < L; i += 256) {
            uint32_t k = keys[i];
            if ((k & maskhi) == prefix)
                atomicAdd(&hist[warp][(k >> shift) & 255], 1);
        }
        __syncthreads();
        for (int i = tid; i < 256; i += 256) {
            int s = 0;
#pragma unroll
            for (int w = 0; w < 8; w++) s += hist[w][i];
            fin[i] = s;
        }
        __syncthreads();
        if (tid == 0) {
            int need = sh_need, cum = 0, d;
            for (d = 255; d >= 0; d--) {
                int c = fin[d];
                if (cum + c >= need) { sh_need = need - cum; break; }
                cum += c;
            }
            sh_prefix = prefix | ((uint32_t)d << shift);
        }
        __syncthreads();
    }
    uint32_t T = sh_prefix;
    int take_eq = sh_need;
    for (int i = tid; i < L; i += 256) {
        uint32_t k = keys[i];
        if (k > T) {
            int p = atomicAdd(&sh_cnt, 1);
            g_top[bh * NTOP + p] = i;
        } else if (k == T) {
            int r = 0;
            for (int j = 0; j < i; j++) if (keys[j] == T) r++;
            if (r < take_eq) {
                int p = atomicAdd(&sh_cnt, 1);
                g_top[bh * NTOP + p] = i;
            }
        }
    }
}

// ---------------------------------------------------------------------------
// sumV: float4 partials, deep MLP.
// ---------------------------------------------------------------------------
__global__ void sumv_part_kernel(const float* __restrict__ V) {
    int blk = blockIdx.x;
    int bh = blk >> 3, p = blk & 7;
    int tid = threadIdx.x;
    int d4 = tid & 15, r0 = tid >> 4;
    const float4* vb = (const float4*)(V + ((size_t)bh * S + (size_t)p * 256) * D);
    float4 a = make_float4(0.f, 0.f, 0.f, 0.f);
#pragma unroll
    for (int j = 0; j < 16; j++) {
        float4 v = vb[(size_t)(j * 16 + r0) * 16 + d4];
        a.x += v.x; a.y += v.y; a.z += v.z; a.w += v.w;
    }
    __shared__ float4 red[256];
    red[tid] = a;
    __syncthreads();
    for (int s = 128; s >= 16; s >>= 1) {
        if (tid < s) {
            red[tid].x += red[tid + s].x; red[tid].y += red[tid + s].y;
            red[tid].z += red[tid + s].z; red[tid].w += red[tid + s].w;
        }
        __syncthreads();
    }
    if (tid < 16) ((float4*)g_part)[(bh * 8 + p) * 16 + tid] = red[tid];
}

// ---------------------------------------------------------------------------
// fill (fused sumv reduce): block reduces the 8 partials once into smem,
// then streams the broadcast row to its 1KB-float4 output slice.
// ---------------------------------------------------------------------------
__global__ void fill_kernel(float4* __restrict__ out) {
    int i = blockIdx.x * 256 + threadIdx.x;      // element in units of float4
    int bh = i >> 15;                            // 32768 float4 per bh
    __shared__ float4 sv[16];
    if (threadIdx.x < 16) {
        float4 a = make_float4(0.f, 0.f, 0.f, 0.f);
#pragma unroll
        for (int p = 0; p < 8; p++) {
            float4 v = ((const float4*)g_part)[(bh * 8 + p) * 16 + threadIdx.x];
            a.x += v.x; a.y += v.y; a.z += v.z; a.w += v.w;
        }
        sv[threadIdx.x] = a;
    }
    __syncthreads();
    out[i] = sv[i & 15];
}

// ---------------------------------------------------------------------------
// Attention partials, no max-subtraction, packed f32x2 FMA (FFMA2) in both
// GEMM loops. cp.async pipeline: V_t during QK_t; K_{t+1} during PV_t.
// ---------------------------------------------------------------------------
__global__ void __launch_bounds__(160, 5) attn_kernel(const float* __restrict__ Q,
                                                      const float* __restrict__ K,
                                                      const float* __restrict__ V) {
    int bid = blockIdx.x;
    int split = bid & (NSPLIT - 1);
    int chunk = (bid >> 3) & 1;
    int bh = bid >> 4;
    int tid = threadIdx.x, w = tid >> 5, lane = tid & 31;

    __shared__ float4 Kb[64][17];
    __shared__ float4 Vb[64][17];
    __shared__ __align__(16) float Qs[QCH][64];
    __shared__ float4 Ps[5][64];

    const float4* Kb4 = (const float4*)(K + (size_t)bh * S * D);
    const float4* Vb4 = (const float4*)(V + (size_t)bh * S * D);

    // prefetch K tile 0
    {
        int kbase = split * 256;
        for (int i = tid; i < 1024; i += 160) {
            int s = i >> 4, c = i & 15;
            cp_async16(&Kb[s][c], &Kb4[(size_t)(kbase + s) * 16 + c]);
        }
        CP_COMMIT();
    }
    for (int i = tid; i < QCH * 64; i += 160) {
        int q = i >> 6, d = i & 63;
        int qrow = g_top[bh * NTOP + chunk * QCH + q];
        Qs[q][d] = Q[((size_t)bh * L + qrow) * D + d];
    }

    int sg = lane >> 3, dg = lane & 7;
    float lsum[4] = {0.f, 0.f, 0.f, 0.f};
    u64 accp[4][4];
#pragma unroll
    for (int qq = 0; qq < 4; qq++)
#pragma unroll
        for (int j = 0; j < 4; j++) accp[qq][j] = 0ull;

#pragma unroll
    for (int t = 0; t < 4; t++) {
        int kbase = split * 256 + t * 64;
        CP_WAIT0();
        __syncthreads();                      // K_t ready; Vb/Ps free

        // prefetch V_t (overlaps with QK)
        for (int i = tid; i < 1024; i += 160) {
            int s = i >> 4, c = i & 15;
            cp_async16(&Vb[s][c], &Vb4[(size_t)(kbase + s) * 16 + c]);
        }
        CP_COMMIT();

        // QK: packed pairwise dots; keys (lane, lane+32) for 4 queries
        u64 s0p[4] = {0ull, 0ull, 0ull, 0ull}, s1p[4] = {0ull, 0ull, 0ull, 0ull};
#pragma unroll
        for (int d4 = 0; d4 < 16; d4++) {
            ulonglong2 k0 = *(const ulonglong2*)&Kb[lane][d4];
            ulonglong2 k1 = *(const ulonglong2*)&Kb[lane + 32][d4];
#pragma unroll
            for (int qq = 0; qq < 4; qq++) {
                ulonglong2 a = *(const ulonglong2*)&Qs[4 * w + qq][d4 * 4];
                s0p[qq] = ffma2(a.x, k0.x, s0p[qq]);
                s0p[qq] = ffma2(a.y, k0.y, s0p[qq]);
                s1p[qq] = ffma2(a.x, k1.x, s1p[qq]);
                s1p[qq] = ffma2(a.y, k1.y, s1p[qq]);
            }
        }
        float pv0[4], pv1[4];
#pragma unroll
        for (int qq = 0; qq < 4; qq++) {
            float2 t0 = unpack2(s0p[qq]);
            float2 t1 = unpack2(s1p[qq]);
            pv0[qq] = __expf((t0.x + t0.y) * 0.125f);
            pv1[qq] = __expf((t1.x + t1.y) * 0.125f);
            lsum[qq] += pv0[qq] + pv1[qq];
        }
        Ps[w][lane]      = make_float4(pv0[0], pv0[1], pv0[2], pv0[3]);
        Ps[w][lane + 32] = make_float4(pv1[0], pv1[1], pv1[2], pv1[3]);

        CP_WAIT0();
        __syncthreads();                      // V_t ready; done reading Kb

        // prefetch K_{t+1} (overlaps with PV)
        if (t < 3) {
            int nbase = kbase + 64;
            for (int i = tid; i < 1024; i += 160) {
                int s = i >> 4, c = i & 15;
                cp_async16(&Kb[s][c], &Kb4[(size_t)(nbase + s) * 16 + c]);
            }
            CP_COMMIT();
        }

        // PV: thread handles keys [sg*16,+16), dims [dg*4,+4) & [(dg+8)*4,+4)
#pragma unroll
        for (int i = 0; i < 16; i++) {
            int s = sg * 16 + i;
            float4 p  = Ps[w][s];
            ulonglong2 va = *(const ulonglong2*)&Vb[s][dg];
            ulonglong2 vb = *(const ulonglong2*)&Vb[s][dg + 8];
            u64 p2[4] = {pack2(p.x), pack2(p.y), pack2(p.z), pack2(p.w)};
#pragma unroll
            for (int qq = 0; qq < 4; qq++) {
                accp[qq][0] = ffma2(p2[qq], va.x, accp[qq][0]);
                accp[qq][1] = ffma2(p2[qq], va.y, accp[qq][1]);
                accp[qq][2] = ffma2(p2[qq], vb.x, accp[qq][2]);
                accp[qq][3] = ffma2(p2[qq], vb.y, accp[qq][3]);
            }
        }
    }

    // one-time reductions: lsum over 32 lanes; acc over the 4 sgroups
#pragma unroll
    for (int qq = 0; qq < 4; qq++) {
#pragma unroll
        for (int o = 16; o; o >>= 1)
            lsum[qq] += __shfl_xor_sync(0xffffffffu, lsum[qq], o);
#pragma unroll
        for (int j = 0; j < 4; j++) {
#pragma unroll
            for (int o = 8; o <= 16; o <<= 1) {
                u64 got = __shfl_xor_sync(0xffffffffu, accp[qq][j], o);
                accp[qq][j] = fadd2(accp[qq][j], got);
            }
        }
    }

    if (lane < 8) {
#pragma unroll
        for (int qq = 0; qq < 4; qq++) {
            int pa = (bh * NTOP + chunk * QCH + 4 * w + qq) * NSPLIT + split;
            ((ulonglong2*)g_acc)[pa * 16 + dg]     = make_ulonglong2(accp[qq][0], accp[qq][1]);
            ((ulonglong2*)g_acc)[pa * 16 + 8 + dg] = make_ulonglong2(accp[qq][2], accp[qq][3]);
        }
    }
    if (lane == 0) {
#pragma unroll
        for (int qq = 0; qq < 4; qq++) {
            int pa = (bh * NTOP + chunk * QCH + 4 * w + qq) * NSPLIT + split;
            g_am[pa] = 0.f; g_al[pa] = lsum[qq];
        }
    }
}

// ---------------------------------------------------------------------------
// Merge the 8 split partials per (bh, q) and write the output row.
// ---------------------------------------------------------------------------
__global__ void merge_kernel(float* __restrict__ out) {
    int w = (blockIdx.x * blockDim.x + threadIdx.x) >> 5;
    int lane = threadIdx.x & 31;
    if (w >= BH * NTOP) return;
    int bh = w / NTOP, qi = w % NTOP;
    int base = w * NSPLIT;

    float Lsum = 0.f, o0 = 0.f, o1 = 0.f;
#pragma unroll
    for (int s = 0; s < NSPLIT; s++) {
        Lsum += g_al[base + s];
        o0 += g_acc[(base + s) * D + lane];
        o1 += g_acc[(base + s) * D + lane + 32];
    }
    int row = g_top[bh * NTOP + qi];
    size_t orow = ((size_t)bh * L + row) * D;
    float inv = 1.0f / Lsum;
    out[orow + lane]      = o0 * inv;
    out[orow + lane + 32] = o1 * inv;
}

// ---------------------------------------------------------------------------
// Launch DAG (graph-captured fork-join):
//   main stream: compute_M -> topk -> attn -> [join] -> merge
//   side stream: sumv_part -> fill   (independent until merge)
// Streams/events are host objects (no device memory); created fresh per call
// and intentionally not destroyed (kernel_launch runs twice: correctness +
// capture; destroying a capture-participating stream would invalidate it).
// ---------------------------------------------------------------------------
extern "C" void kernel_launch(void* const* d_in, const int* in_sizes, int n_in,
                              void* d_out, int out_size) {
    const float* q = (const float*)d_in[0];
    const float* k = (const float*)d_in[1];
    const float* v = (const float*)d_in[2];
    float* out = (float*)d_out;

    cudaStream_t s1;
    cudaStreamCreateWithFlags(&s1, cudaStreamNonBlocking);
    cudaEvent_t e_fork, e_join;
    cudaEventCreateWithFlags(&e_fork, cudaEventDisableTiming);
    cudaEventCreateWithFlags(&e_join, cudaEventDisableTiming);

    // fork side stream off the (per-thread default) capture stream
    cudaEventRecord(e_fork, 0);
    cudaStreamWaitEvent(s1, e_fork, 0);
    sumv_part_kernel<<<BH * 8, 256, 0, s1>>>(v);
    fill_kernel<<<(B * H * L * D / 4) / 256, 256, 0, s1>>>((float4*)out);
    cudaEventRecord(e_join, s1);

    // main chain
    compute_M_kernel<<<BH * (L / 32), 256>>>(q, k);
    topk_kernel<<<BH, 256>>>();
    attn_kernel<<<BH * 2 * NSPLIT, 160>>>(q, k, v);

    // join: merge overwrites top rows, so it must follow fill
    cudaStreamWaitEvent(0, e_join, 0);
    merge_kernel<<<(BH * NTOP * 32 + 255) / 256, 256>>>(out);
}

// round 14
// speedup vs baseline: 1.1926x; 1.1330x over previous
#include <cuda_runtime.h>
#include <math_constants.h>
#include <cstdint>

constexpr int B = 4, L = 2048, H = 8, D = 64, S = 2048;
constexpr int U = 40, NTOP = 40, BH = B * H;
constexpr int NSPLIT = 8;                // S split into 8 x 256 keys (4 tiles of 64)
constexpr int QCH = 20;                  // queries per chunk (2 chunks = 40)

__device__ float    g_M[BH * L];
__device__ int      g_top[BH * NTOP];
__device__ float    g_part[BH * 8 * D];
__device__ float    g_am[BH * NTOP * NSPLIT];
__device__ float    g_al[BH * NTOP * NSPLIT];
__device__ float    g_acc[BH * NTOP * NSPLIT * D];

// ---------------------------------------------------------------------------
__device__ __forceinline__ void cp_async16(void* smem, const void* gmem) {
    uint32_t s = (uint32_t)__cvta_generic_to_shared(smem);
    asm volatile("cp.async.cg.shared.global [%0], [%1], 16;\n" :: "r"(s), "l"(gmem));
}
#define CP_COMMIT() asm volatile("cp.async.commit_group;\n" ::: "memory")
#define CP_WAIT0()  asm volatile("cp.async.wait_group 0;\n" ::: "memory")

// ---- packed fp32x2 ops (Blackwell FFMA2 path) ------------------------------
typedef unsigned long long u64;
__device__ __forceinline__ u64 ffma2(u64 a, u64 b, u64 c) {
    u64 d; asm("fma.rn.f32x2 %0, %1, %2, %3;" : "=l"(d) : "l"(a), "l"(b), "l"(c));
    return d;
}
__device__ __forceinline__ u64 fadd2(u64 a, u64 b) {
    u64 d; asm("add.rn.f32x2 %0, %1, %2;" : "=l"(d) : "l"(a), "l"(b));
    return d;
}
__device__ __forceinline__ u64 pack2(float x) {
    u64 d; asm("mov.b64 %0, {%1, %1};" : "=l"(d) : "f"(x));
    return d;
}
__device__ __forceinline__ float2 unpack2(u64 a) {
    float lo, hi; asm("mov.b64 {%0, %1}, %2;" : "=f"(lo), "=f"(hi) : "l"(a));
    return make_float2(lo, hi);
}

// ---------------------------------------------------------------------------
// threefry2x32 (matches jax/_src/prng.py), partitionable path.
// ---------------------------------------------------------------------------
__device__ __forceinline__ uint2 threefry2x32(uint32_t k0, uint32_t k1,
                                              uint32_t x0, uint32_t x1) {
    uint32_t ks2 = k0 ^ k1 ^ 0x1BD11BDAu;
    x0 += k0; x1 += k1;
#define TF_RND(r) { x0 += x1; x1 = (x1 << (r)) | (x1 >> (32 - (r))); x1 ^= x0; }
    TF_RND(13) TF_RND(15) TF_RND(26) TF_RND(6)
    x0 += k1;  x1 += ks2 + 1u;
    TF_RND(17) TF_RND(29) TF_RND(16) TF_RND(24)
    x0 += ks2; x1 += k0 + 2u;
    TF_RND(13) TF_RND(15) TF_RND(26) TF_RND(6)
    x0 += k0;  x1 += k1 + 3u;
    TF_RND(17) TF_RND(29) TF_RND(16) TF_RND(24)
    x0 += k1;  x1 += ks2 + 4u;
    TF_RND(13) TF_RND(15) TF_RND(26) TF_RND(6)
    x0 += ks2; x1 += k0 + 5u;
#undef TF_RND
    return make_uint2(x0, x1);
}

// ---------------------------------------------------------------------------
// M: indices generated inline. 8-lane group per l-row, 32 rows/block.
// MLP=8 per group, 7-shuffle butterfly per 8 samples. grid = BH*L/32.
// ---------------------------------------------------------------------------
__global__ void __launch_bounds__(256, 5)
compute_M_kernel(const float* __restrict__ Q, const float* __restrict__ K) {
    int tid = threadIdx.x;
    int bh = blockIdx.x >> 6;
    int block_l = (blockIdx.x & 63) * 32;

    __shared__ int sidx[32 * U];
    {
        uint2 k2 = threefry2x32(0u, 42u, 0u, 1u);
        for (int i = tid; i < 32 * U; i += 256) {
            uint32_t gi = (uint32_t)(block_l * U + i);
            uint2 r = threefry2x32(k2.x, k2.y, 0u, gi);
            sidx[i] = (int)((r.x ^ r.y) & (uint32_t)(S - 1));
        }
    }
    __syncthreads();

    int warp = tid >> 5, lane = tid & 31;
    int g = lane >> 3, li = lane & 7;
    int r = warp * 4 + g;
    int l = block_l + r;
    const int* myidx = &sidx[r * U];

    const float4* Kb4 = (const float4*)(K + (size_t)bh * S * D);
    const float4* q4  = (const float4*)(Q + ((size_t)bh * L + l) * D);
    float4 qa = q4[li], qb = q4[li + 8];

    float mx = -CUDART_INF_F, sm = 0.f;
#pragma unroll
    for (int round = 0; round < 5; round++) {
        float p[8];
#pragma unroll
        for (int half = 0; half < 2; half++) {
            float4 ka[4], kb[4];
#pragma unroll
            for (int t = 0; t < 4; t++) {
                int kidx = myidx[round * 8 + half * 4 + t];
                ka[t] = Kb4[kidx * 16 + li];
                kb[t] = Kb4[kidx * 16 + 8 + li];
            }
#pragma unroll
            for (int t = 0; t < 4; t++) {
                p[half * 4 + t] =
                    qa.x * ka[t].x + qa.y * ka[t].y + qa.z * ka[t].z + qa.w * ka[t].w +
                    qb.x * kb[t].x + qb.y * kb[t].y + qb.z * kb[t].z + qb.w * kb[t].w;
            }
        }
#pragma unroll
        for (int o = 4; o; o >>= 1) {
#pragma unroll
            for (int j = 0; j < o; j++) {
                float a = p[j], b = p[j + o];
                float sel = (li & o) ? a : b;
                float got = __shfl_xor_sync(0xffffffffu, sel, o);
                p[j] = ((li & o) ? b : a) + got;
            }
        }
        mx = fmaxf(mx, p[0]);
        sm += p[0];
    }
#pragma unroll
    for (int o = 4; o; o >>= 1) {
        mx = fmaxf(mx, __shfl_xor_sync(0xffffffffu, mx, o));
        sm += __shfl_xor_sync(0xffffffffu, sm, o);
    }
    if (li == 0) g_M[bh * L + l] = mx - sm * (1.0f / (float)S);
}

// ---------------------------------------------------------------------------
// Exact top-40 per (bh): 4-pass radix select, keys in registers, single
// atomic histogram, parallel Hillis-Steele suffix-scan (no serial tid0 walk).
// g_top receives the SET of top indices (order irrelevant downstream).
// ---------------------------------------------------------------------------
__global__ void topk_kernel() {
    int bh = blockIdx.x, tid = threadIdx.x;       // 256 threads
    __shared__ uint32_t keys[L];                  // only for rare tie-rank loop
    __shared__ int hist[256];
    __shared__ int sfx[256];
    __shared__ uint32_t sh_prefix;
    __shared__ int sh_need, sh_cnt;

    uint32_t kreg[8];
#pragma unroll
    for (int j = 0; j < 8; j++) {
        uint32_t b = __float_as_uint(g_M[bh * L + tid + 256 * j]);
        uint32_t kk = (b & 0x80000000u) ? ~b : (b | 0x80000000u);
        kreg[j] = kk;
        keys[tid + 256 * j] = kk;
    }
    if (tid == 0) { sh_prefix = 0u; sh_need = NTOP; sh_cnt = 0; }
    __syncthreads();

#pragma unroll
    for (int shift = 24; shift >= 0; shift -= 8) {
        hist[tid] = 0;
        __syncthreads();
        uint32_t prefix = sh_prefix;
        uint32_t maskhi = (shift == 24) ? 0u : (0xFFFFFFFFu << (shift + 8));
#pragma unroll
        for (int j = 0; j < 8; j++) {
            uint32_t kk = kreg[j];
            if ((kk & maskhi) == prefix)
                atomicAdd(&hist[(kk >> shift) & 255], 1);
        }
        __syncthreads();
        // parallel suffix sums: sfx[i] = sum_{j >= i} hist[j]
        sfx[tid] = hist[tid];
        __syncthreads();
#pragma unroll
        for (int off = 1; off < 256; off <<= 1) {
            int add = (tid + off < 256) ? sfx[tid + off] : 0;
            __syncthreads();
            sfx[tid] += add;
            __syncthreads();
        }
        // unique crossing bin d: sfx[d] >= need && sfx[d+1] < need
        int need = sh_need;
        int nxt = (tid < 255) ? sfx[tid + 1] : 0;
        if (sfx[tid] >= need && nxt < need) {
            sh_prefix = prefix | ((uint32_t)tid << shift);
            sh_need = need - nxt;
        }
        __syncthreads();
    }

    uint32_t T = sh_prefix;
    int take_eq = sh_need;
#pragma unroll
    for (int j = 0; j < 8; j++) {
        uint32_t kk = kreg[j];
        int i = tid + 256 * j;
        if (kk > T) {
            int p = atomicAdd(&sh_cnt, 1);
            g_top[bh * NTOP + p] = i;
        } else if (kk == T) {
            int r = 0;
            for (int jj = 0; jj < i; jj++) if (keys[jj] == T) r++;
            if (r < take_eq) {
                int p = atomicAdd(&sh_cnt, 1);
                g_top[bh * NTOP + p] = i;
            }
        }
    }
}

// ---------------------------------------------------------------------------
// sumV: float4 partials, deep MLP.
// ---------------------------------------------------------------------------
__global__ void sumv_part_kernel(const float* __restrict__ V) {
    int blk = blockIdx.x;
    int bh = blk >> 3, p = blk & 7;
    int tid = threadIdx.x;
    int d4 = tid & 15, r0 = tid >> 4;
    const float4* vb = (const float4*)(V + ((size_t)bh * S + (size_t)p * 256) * D);
    float4 a = make_float4(0.f, 0.f, 0.f, 0.f);
#pragma unroll
    for (int j = 0; j < 16; j++) {
        float4 v = vb[(size_t)(j * 16 + r0) * 16 + d4];
        a.x += v.x; a.y += v.y; a.z += v.z; a.w += v.w;
    }
    __shared__ float4 red[256];
    red[tid] = a;
    __syncthreads();
    for (int s = 128; s >= 16; s >>= 1) {
        if (tid < s) {
            red[tid].x += red[tid + s].x; red[tid].y += red[tid + s].y;
            red[tid].z += red[tid + s].z; red[tid].w += red[tid + s].w;
        }
        __syncthreads();
    }
    if (tid < 16) ((float4*)g_part)[(bh * 8 + p) * 16 + tid] = red[tid];
}

// ---------------------------------------------------------------------------
// fill (fused sumv reduce): block reduces the 8 partials once into smem,
// then streams the broadcast row to its 1KB-float4 output slice.
// ---------------------------------------------------------------------------
__global__ void fill_kernel(float4* __restrict__ out) {
    int i = blockIdx.x * 256 + threadIdx.x;      // element in units of float4
    int bh = i >> 15;                            // 32768 float4 per bh
    __shared__ float4 sv[16];
    if (threadIdx.x < 16) {
        float4 a = make_float4(0.f, 0.f, 0.f, 0.f);
#pragma unroll
        for (int p = 0; p < 8; p++) {
            float4 v = ((const float4*)g_part)[(bh * 8 + p) * 16 + threadIdx.x];
            a.x += v.x; a.y += v.y; a.z += v.z; a.w += v.w;
        }
        sv[threadIdx.x] = a;
    }
    __syncthreads();
    out[i] = sv[i & 15];
}

// ---------------------------------------------------------------------------
// Attention partials, no max-subtraction, packed f32x2 FMA (FFMA2) in both
// GEMM loops. cp.async pipeline: V_t during QK_t; K_{t+1} during PV_t.
// ---------------------------------------------------------------------------
__global__ void __launch_bounds__(160, 5) attn_kernel(const float* __restrict__ Q,
                                                      const float* __restrict__ K,
                                                      const float* __restrict__ V) {
    int bid = blockIdx.x;
    int split = bid & (NSPLIT - 1);
    int chunk = (bid >> 3) & 1;
    int bh = bid >> 4;
    int tid = threadIdx.x, w = tid >> 5, lane = tid & 31;

    __shared__ float4 Kb[64][17];
    __shared__ float4 Vb[64][17];
    __shared__ __align__(16) float Qs[QCH][64];
    __shared__ float4 Ps[5][64];

    const float4* Kb4 = (const float4*)(K + (size_t)bh * S * D);
    const float4* Vb4 = (const float4*)(V + (size_t)bh * S * D);

    // prefetch K tile 0
    {
        int kbase = split * 256;
        for (int i = tid; i < 1024; i += 160) {
            int s = i >> 4, c = i & 15;
            cp_async16(&Kb[s][c], &Kb4[(size_t)(kbase + s) * 16 + c]);
        }
        CP_COMMIT();
    }
    for (int i = tid; i < QCH * 64; i += 160) {
        int q = i >> 6, d = i & 63;
        int qrow = g_top[bh * NTOP + chunk * QCH + q];
        Qs[q][d] = Q[((size_t)bh * L + qrow) * D + d];
    }

    int sg = lane >> 3, dg = lane & 7;
    float lsum[4] = {0.f, 0.f, 0.f, 0.f};
    u64 accp[4][4];
#pragma unroll
    for (int qq = 0; qq < 4; qq++)
#pragma unroll
        for (int j = 0; j < 4; j++) accp[qq][j] = 0ull;

#pragma unroll
    for (int t = 0; t < 4; t++) {
        int kbase = split * 256 + t * 64;
        CP_WAIT0();
        __syncthreads();                      // K_t ready; Vb/Ps free

        // prefetch V_t (overlaps with QK)
        for (int i = tid; i < 1024; i += 160) {
            int s = i >> 4, c = i & 15;
            cp_async16(&Vb[s][c], &Vb4[(size_t)(kbase + s) * 16 + c]);
        }
        CP_COMMIT();

        // QK: packed pairwise dots; keys (lane, lane+32) for 4 queries
        u64 s0p[4] = {0ull, 0ull, 0ull, 0ull}, s1p[4] = {0ull, 0ull, 0ull, 0ull};
#pragma unroll
        for (int d4 = 0; d4 < 16; d4++) {
            ulonglong2 k0 = *(const ulonglong2*)&Kb[lane][d4];
            ulonglong2 k1 = *(const ulonglong2*)&Kb[lane + 32][d4];
#pragma unroll
            for (int qq = 0; qq < 4; qq++) {
                ulonglong2 a = *(const ulonglong2*)&Qs[4 * w + qq][d4 * 4];
                s0p[qq] = ffma2(a.x, k0.x, s0p[qq]);
                s0p[qq] = ffma2(a.y, k0.y, s0p[qq]);
                s1p[qq] = ffma2(a.x, k1.x, s1p[qq]);
                s1p[qq] = ffma2(a.y, k1.y, s1p[qq]);
            }
        }
        float pv0[4], pv1[4];
#pragma unroll
        for (int qq = 0; qq < 4; qq++) {
            float2 t0 = unpack2(s0p[qq]);
            float2 t1 = unpack2(s1p[qq]);
            pv0[qq] = __expf((t0.x + t0.y) * 0.125f);
            pv1[qq] = __expf((t1.x + t1.y) * 0.125f);
            lsum[qq] += pv0[qq] + pv1[qq];
        }
        Ps[w][lane]      = make_float4(pv0[0], pv0[1], pv0[2], pv0[3]);
        Ps[w][lane + 32] = make_float4(pv1[0], pv1[1], pv1[2], pv1[3]);

        CP_WAIT0();
        __syncthreads();                      // V_t ready; done reading Kb

        // prefetch K_{t+1} (overlaps with PV)
        if (t < 3) {
            int nbase = kbase + 64;
            for (int i = tid; i < 1024; i += 160) {
                int s = i >> 4, c = i & 15;
                cp_async16(&Kb[s][c], &Kb4[(size_t)(nbase + s) * 16 + c]);
            }
            CP_COMMIT();
        }

        // PV: thread handles keys [sg*16,+16), dims [dg*4,+4) & [(dg+8)*4,+4)
#pragma unroll
        for (int i = 0; i < 16; i++) {
            int s = sg * 16 + i;
            float4 p  = Ps[w][s];
            ulonglong2 va = *(const ulonglong2*)&Vb[s][dg];
            ulonglong2 vb = *(const ulonglong2*)&Vb[s][dg + 8];
            u64 p2[4] = {pack2(p.x), pack2(p.y), pack2(p.z), pack2(p.w)};
#pragma unroll
            for (int qq = 0; qq < 4; qq++) {
                accp[qq][0] = ffma2(p2[qq], va.x, accp[qq][0]);
                accp[qq][1] = ffma2(p2[qq], va.y, accp[qq][1]);
                accp[qq][2] = ffma2(p2[qq], vb.x, accp[qq][2]);
                accp[qq][3] = ffma2(p2[qq], vb.y, accp[qq][3]);
            }
        }
    }

    // one-time reductions: lsum over 32 lanes; acc over the 4 sgroups
#pragma unroll
    for (int qq = 0; qq < 4; qq++) {
#pragma unroll
        for (int o = 16; o; o >>= 1)
            lsum[qq] += __shfl_xor_sync(0xffffffffu, lsum[qq], o);
#pragma unroll
        for (int j = 0; j < 4; j++) {
#pragma unroll
            for (int o = 8; o <= 16; o <<= 1) {
                u64 got = __shfl_xor_sync(0xffffffffu, accp[qq][j], o);
                accp[qq][j] = fadd2(accp[qq][j], got);
            }
        }
    }

    if (lane < 8) {
#pragma unroll
        for (int qq = 0; qq < 4; qq++) {
            int pa = (bh * NTOP + chunk * QCH + 4 * w + qq) * NSPLIT + split;
            ((ulonglong2*)g_acc)[pa * 16 + dg]     = make_ulonglong2(accp[qq][0], accp[qq][1]);
            ((ulonglong2*)g_acc)[pa * 16 + 8 + dg] = make_ulonglong2(accp[qq][2], accp[qq][3]);
        }
    }
    if (lane == 0) {
#pragma unroll
        for (int qq = 0; qq < 4; qq++) {
            int pa = (bh * NTOP + chunk * QCH + 4 * w + qq) * NSPLIT + split;
            g_am[pa] = 0.f; g_al[pa] = lsum[qq];
        }
    }
}

// ---------------------------------------------------------------------------
// Merge the 8 split partials per (bh, q) and write the output row.
// ---------------------------------------------------------------------------
__global__ void merge_kernel(float* __restrict__ out) {
    int w = (blockIdx.x * blockDim.x + threadIdx.x) >> 5;
    int lane = threadIdx.x & 31;
    if (w >= BH * NTOP) return;
    int bh = w / NTOP, qi = w % NTOP;
    int base = w * NSPLIT;

    float Lsum = 0.f, o0 = 0.f, o1 = 0.f;
#pragma unroll
    for (int s = 0; s < NSPLIT; s++) {
        Lsum += g_al[base + s];
        o0 += g_acc[(base + s) * D + lane];
        o1 += g_acc[(base + s) * D + lane + 32];
    }
    int row = g_top[bh * NTOP + qi];
    size_t orow = ((size_t)bh * L + row) * D;
    float inv = 1.0f / Lsum;
    out[orow + lane]      = o0 * inv;
    out[orow + lane + 32] = o1 * inv;
}

// ---------------------------------------------------------------------------
// Launch DAG (graph-captured fork-join):
//   main stream: compute_M -> topk -> attn -> [join] -> merge
//   side stream: sumv_part -> fill   (independent until merge)
// Streams/events are host objects (no device memory); created fresh per call
// and intentionally not destroyed (kernel_launch runs twice: correctness +
// capture; destroying a capture-participating stream would invalidate it).
// ---------------------------------------------------------------------------
extern "C" void kernel_launch(void* const* d_in, const int* in_sizes, int n_in,
                              void* d_out, int out_size) {
    const float* q = (const float*)d_in[0];
    const float* k = (const float*)d_in[1];
    const float* v = (const float*)d_in[2];
    float* out = (float*)d_out;

    cudaStream_t s1;
    cudaStreamCreateWithFlags(&s1, cudaStreamNonBlocking);
    cudaEvent_t e_fork, e_join;
    cudaEventCreateWithFlags(&e_fork, cudaEventDisableTiming);
    cudaEventCreateWithFlags(&e_join, cudaEventDisableTiming);

    // fork side stream off the (per-thread default) capture stream
    cudaEventRecord(e_fork, 0);
    cudaStreamWaitEvent(s1, e_fork, 0);
    sumv_part_kernel<<<BH * 8, 256, 0, s1>>>(v);
    fill_kernel<<<(B * H * L * D / 4) / 256, 256, 0, s1>>>((float4*)out);
    cudaEventRecord(e_join, s1);

    // main chain
    compute_M_kernel<<<BH * (L / 32), 256>>>(q, k);
    topk_kernel<<<BH, 256>>>();
    attn_kernel<<<BH * 2 * NSPLIT, 160>>>(q, k, v);

    // join: merge overwrites top rows, so it must follow fill
    cudaStreamWaitEvent(0, e_join, 0);
    merge_kernel<<<(BH * NTOP * 32 + 255) / 256, 256>>>(out);
}

// round 15
// speedup vs baseline: 1.2218x; 1.0245x over previous
#include <cuda_runtime.h>
#include <math_constants.h>
#include <cstdint>

constexpr int B = 4, L = 2048, H = 8, D = 64, S = 2048;
constexpr int U = 40, NTOP = 40, BH = B * H;
constexpr int NSPLIT = 8;                // S split into 8 x 256 keys (4 tiles of 64)
constexpr int QCH = 20;                  // queries per chunk (2 chunks = 40)

__device__ float    g_M[BH * L];
__device__ int      g_top[BH * NTOP];
__device__ float    g_part[BH * 8 * D];
__device__ float    g_am[BH * NTOP * NSPLIT];
__device__ float    g_al[BH * NTOP * NSPLIT];
__device__ float    g_acc[BH * NTOP * NSPLIT * D];

// ---------------------------------------------------------------------------
__device__ __forceinline__ void cp_async16(void* smem, const void* gmem) {
    uint32_t s = (uint32_t)__cvta_generic_to_shared(smem);
    asm volatile("cp.async.cg.shared.global [%0], [%1], 16;\n" :: "r"(s), "l"(gmem));
}
#define CP_COMMIT() asm volatile("cp.async.commit_group;\n" ::: "memory")
#define CP_WAIT0()  asm volatile("cp.async.wait_group 0;\n" ::: "memory")

// ---- packed fp32x2 ops (Blackwell FFMA2 path) ------------------------------
typedef unsigned long long u64;
__device__ __forceinline__ u64 ffma2(u64 a, u64 b, u64 c) {
    u64 d; asm("fma.rn.f32x2 %0, %1, %2, %3;" : "=l"(d) : "l"(a), "l"(b), "l"(c));
    return d;
}
__device__ __forceinline__ u64 fadd2(u64 a, u64 b) {
    u64 d; asm("add.rn.f32x2 %0, %1, %2;" : "=l"(d) : "l"(a), "l"(b));
    return d;
}
__device__ __forceinline__ u64 pack2(float x) {
    u64 d; asm("mov.b64 %0, {%1, %1};" : "=l"(d) : "f"(x));
    return d;
}
__device__ __forceinline__ float2 unpack2(u64 a) {
    float lo, hi; asm("mov.b64 {%0, %1}, %2;" : "=f"(lo), "=f"(hi) : "l"(a));
    return make_float2(lo, hi);
}

// ---------------------------------------------------------------------------
// threefry2x32 (matches jax/_src/prng.py), partitionable path.
// ---------------------------------------------------------------------------
__device__ __forceinline__ uint2 threefry2x32(uint32_t k0, uint32_t k1,
                                              uint32_t x0, uint32_t x1) {
    uint32_t ks2 = k0 ^ k1 ^ 0x1BD11BDAu;
    x0 += k0; x1 += k1;
#define TF_RND(r) { x0 += x1; x1 = (x1 << (r)) | (x1 >> (32 - (r))); x1 ^= x0; }
    TF_RND(13) TF_RND(15) TF_RND(26) TF_RND(6)
    x0 += k1;  x1 += ks2 + 1u;
    TF_RND(17) TF_RND(29) TF_RND(16) TF_RND(24)
    x0 += ks2; x1 += k0 + 2u;
    TF_RND(13) TF_RND(15) TF_RND(26) TF_RND(6)
    x0 += k0;  x1 += k1 + 3u;
    TF_RND(17) TF_RND(29) TF_RND(16) TF_RND(24)
    x0 += k1;  x1 += ks2 + 4u;
    TF_RND(13) TF_RND(15) TF_RND(26) TF_RND(6)
    x0 += ks2; x1 += k0 + 5u;
#undef TF_RND
    return make_uint2(x0, x1);
}

// ---------------------------------------------------------------------------
// M: indices generated inline. 8-lane group per l-row, 32 rows/block.
// MLP=8 per group, 7-shuffle butterfly per 8 samples. grid = BH*L/32.
// ---------------------------------------------------------------------------
__global__ void __launch_bounds__(256, 5)
compute_M_kernel(const float* __restrict__ Q, const float* __restrict__ K) {
    int tid = threadIdx.x;
    int bh = blockIdx.x >> 6;
    int block_l = (blockIdx.x & 63) * 32;

    __shared__ int sidx[32 * U];
    {
        uint2 k2 = threefry2x32(0u, 42u, 0u, 1u);
        for (int i = tid; i < 32 * U; i += 256) {
            uint32_t gi = (uint32_t)(block_l * U + i);
            uint2 r = threefry2x32(k2.x, k2.y, 0u, gi);
            sidx[i] = (int)((r.x ^ r.y) & (uint32_t)(S - 1));
        }
    }
    __syncthreads();

    int warp = tid >> 5, lane = tid & 31;
    int g = lane >> 3, li = lane & 7;
    int r = warp * 4 + g;
    int l = block_l + r;
    const int* myidx = &sidx[r * U];

    const float4* Kb4 = (const float4*)(K + (size_t)bh * S * D);
    const float4* q4  = (const float4*)(Q + ((size_t)bh * L + l) * D);
    float4 qa = q4[li], qb = q4[li + 8];

    float mx = -CUDART_INF_F, sm = 0.f;
#pragma unroll
    for (int round = 0; round < 5; round++) {
        float p[8];
#pragma unroll
        for (int half = 0; half < 2; half++) {
            float4 ka[4], kb[4];
#pragma unroll
            for (int t = 0; t < 4; t++) {
                int kidx = myidx[round * 8 + half * 4 + t];
                ka[t] = Kb4[kidx * 16 + li];
                kb[t] = Kb4[kidx * 16 + 8 + li];
            }
#pragma unroll
            for (int t = 0; t < 4; t++) {
                p[half * 4 + t] =
                    qa.x * ka[t].x + qa.y * ka[t].y + qa.z * ka[t].z + qa.w * ka[t].w +
                    qb.x * kb[t].x + qb.y * kb[t].y + qb.z * kb[t].z + qb.w * kb[t].w;
            }
        }
#pragma unroll
        for (int o = 4; o; o >>= 1) {
#pragma unroll
            for (int j = 0; j < o; j++) {
                float a = p[j], b = p[j + o];
                float sel = (li & o) ? a : b;
                float got = __shfl_xor_sync(0xffffffffu, sel, o);
                p[j] = ((li & o) ? b : a) + got;
            }
        }
        mx = fmaxf(mx, p[0]);
        sm += p[0];
    }
#pragma unroll
    for (int o = 4; o; o >>= 1) {
        mx = fmaxf(mx, __shfl_xor_sync(0xffffffffu, mx, o));
        sm += __shfl_xor_sync(0xffffffffu, sm, o);
    }
    if (li == 0) g_M[bh * L + l] = mx - sm * (1.0f / (float)S);
}

// ---------------------------------------------------------------------------
// Exact top-40 per (bh): 4-pass radix select. 1024 threads (2 keys each in
// registers), single atomic histogram, warp-0 register suffix-scan (8 bins
// per lane + 5 shfl_down) -> 3 block barriers per pass instead of ~20.
// g_top receives the SET of top indices (order irrelevant downstream).
// ---------------------------------------------------------------------------
__global__ void __launch_bounds__(1024) topk_kernel() {
    int bh = blockIdx.x, tid = threadIdx.x;       // 1024 threads
    __shared__ uint32_t keys[L];                  // for rare tie-rank loop
    __shared__ int hist[256];
    __shared__ uint32_t sh_prefix;
    __shared__ int sh_need, sh_cnt;

    uint32_t kreg[2];
#pragma unroll
    for (int j = 0; j < 2; j++) {
        uint32_t b = __float_as_uint(g_M[bh * L + tid + 1024 * j]);
        uint32_t kk = (b & 0x80000000u) ? ~b : (b | 0x80000000u);
        kreg[j] = kk;
        keys[tid + 1024 * j] = kk;
    }
    if (tid == 0) { sh_prefix = 0u; sh_need = NTOP; sh_cnt = 0; }

#pragma unroll
    for (int shift = 24; shift >= 0; shift -= 8) {
        if (tid < 256) hist[tid] = 0;
        __syncthreads();                          // hist zeroed; sh_* visible
        uint32_t prefix = sh_prefix;
        uint32_t maskhi = (shift == 24) ? 0u : (0xFFFFFFFFu << (shift + 8));
#pragma unroll
        for (int j = 0; j < 2; j++) {
            uint32_t kk = kreg[j];
            if ((kk & maskhi) == prefix)
                atomicAdd(&hist[(kk >> shift) & 255], 1);
        }
        __syncthreads();                          // hist complete
        if (tid < 32) {
            int lane = tid;
            int b[8];
#pragma unroll
            for (int j = 0; j < 8; j++) b[j] = hist[lane * 8 + j];
            int tot = b[0] + b[1] + b[2] + b[3] + b[4] + b[5] + b[6] + b[7];
            // inclusive suffix of lane totals via shfl_down
            int inc = tot;
#pragma unroll
            for (int off = 1; off < 32; off <<= 1) {
                int v = __shfl_down_sync(0xffffffffu, inc, off);
                if (lane + off < 32) inc += v;
            }
            int higher = inc - tot;               // sum over lanes > lane
            int sfx[9];
            sfx[8] = higher;
#pragma unroll
            for (int j = 7; j >= 0; j--) sfx[j] = sfx[j + 1] + b[j];
            int need = sh_need;
            __syncwarp();                         // all reads of sh_need done
#pragma unroll
            for (int j = 0; j < 8; j++) {
                if (sfx[j] >= need && sfx[j + 1] < need) {
                    sh_prefix = prefix | ((uint32_t)(lane * 8 + j) << shift);
                    sh_need = need - sfx[j + 1];
                }
            }
        }
        __syncthreads();                          // sh_prefix/sh_need published
    }

    uint32_t T = sh_prefix;
    int take_eq = sh_need;
#pragma unroll
    for (int j = 0; j < 2; j++) {
        uint32_t kk = kreg[j];
        int i = tid + 1024 * j;
        if (kk > T) {
            int p = atomicAdd(&sh_cnt, 1);
            g_top[bh * NTOP + p] = i;
        } else if (kk == T) {
            int r = 0;
            for (int jj = 0; jj < i; jj++) if (keys[jj] == T) r++;
            if (r < take_eq) {
                int p = atomicAdd(&sh_cnt, 1);
                g_top[bh * NTOP + p] = i;
            }
        }
    }
}

// ---------------------------------------------------------------------------
// sumV: float4 partials, deep MLP.
// ---------------------------------------------------------------------------
__global__ void sumv_part_kernel(const float* __restrict__ V) {
    int blk = blockIdx.x;
    int bh = blk >> 3, p = blk & 7;
    int tid = threadIdx.x;
    int d4 = tid & 15, r0 = tid >> 4;
    const float4* vb = (const float4*)(V + ((size_t)bh * S + (size_t)p * 256) * D);
    float4 a = make_float4(0.f, 0.f, 0.f, 0.f);
#pragma unroll
    for (int j = 0; j < 16; j++) {
        float4 v = vb[(size_t)(j * 16 + r0) * 16 + d4];
        a.x += v.x; a.y += v.y; a.z += v.z; a.w += v.w;
    }
    __shared__ float4 red[256];
    red[tid] = a;
    __syncthreads();
    for (int s = 128; s >= 16; s >>= 1) {
        if (tid < s) {
            red[tid].x += red[tid + s].x; red[tid].y += red[tid + s].y;
            red[tid].z += red[tid + s].z; red[tid].w += red[tid + s].w;
        }
        __syncthreads();
    }
    if (tid < 16) ((float4*)g_part)[(bh * 8 + p) * 16 + tid] = red[tid];
}

// ---------------------------------------------------------------------------
// fill (fused sumv reduce): block reduces the 8 partials once into smem,
// then streams the broadcast row to its 1KB-float4 output slice.
// ---------------------------------------------------------------------------
__global__ void fill_kernel(float4* __restrict__ out) {
    int i = blockIdx.x * 256 + threadIdx.x;      // element in units of float4
    int bh = i >> 15;                            // 32768 float4 per bh
    __shared__ float4 sv[16];
    if (threadIdx.x < 16) {
        float4 a = make_float4(0.f, 0.f, 0.f, 0.f);
#pragma unroll
        for (int p = 0; p < 8; p++) {
            float4 v = ((const float4*)g_part)[(bh * 8 + p) * 16 + threadIdx.x];
            a.x += v.x; a.y += v.y; a.z += v.z; a.w += v.w;
        }
        sv[threadIdx.x] = a;
    }
    __syncthreads();
    out[i] = sv[i & 15];
}

// ---------------------------------------------------------------------------
// Attention partials, no max-subtraction, packed f32x2 FMA (FFMA2) in both
// GEMM loops. cp.async pipeline: V_t during QK_t; K_{t+1} during PV_t.
// ---------------------------------------------------------------------------
__global__ void __launch_bounds__(160, 5) attn_kernel(const float* __restrict__ Q,
                                                      const float* __restrict__ K,
                                                      const float* __restrict__ V) {
    int bid = blockIdx.x;
    int split = bid & (NSPLIT - 1);
    int chunk = (bid >> 3) & 1;
    int bh = bid >> 4;
    int tid = threadIdx.x, w = tid >> 5, lane = tid & 31;

    __shared__ float4 Kb[64][17];
    __shared__ float4 Vb[64][17];
    __shared__ __align__(16) float Qs[QCH][64];
    __shared__ float4 Ps[5][64];

    const float4* Kb4 = (const float4*)(K + (size_t)bh * S * D);
    const float4* Vb4 = (const float4*)(V + (size_t)bh * S * D);

    // prefetch K tile 0
    {
        int kbase = split * 256;
        for (int i = tid; i < 1024; i += 160) {
            int s = i >> 4, c = i & 15;
            cp_async16(&Kb[s][c], &Kb4[(size_t)(kbase + s) * 16 + c]);
        }
        CP_COMMIT();
    }
    for (int i = tid; i < QCH * 64; i += 160) {
        int q = i >> 6, d = i & 63;
        int qrow = g_top[bh * NTOP + chunk * QCH + q];
        Qs[q][d] = Q[((size_t)bh * L + qrow) * D + d];
    }

    int sg = lane >> 3, dg = lane & 7;
    float lsum[4] = {0.f, 0.f, 0.f, 0.f};
    u64 accp[4][4];
#pragma unroll
    for (int qq = 0; qq < 4; qq++)
#pragma unroll
        for (int j = 0; j < 4; j++) accp[qq][j] = 0ull;

#pragma unroll
    for (int t = 0; t < 4; t++) {
        int kbase = split * 256 + t * 64;
        CP_WAIT0();
        __syncthreads();                      // K_t ready; Vb/Ps free

        // prefetch V_t (overlaps with QK)
        for (int i = tid; i < 1024; i += 160) {
            int s = i >> 4, c = i & 15;
            cp_async16(&Vb[s][c], &Vb4[(size_t)(kbase + s) * 16 + c]);
        }
        CP_COMMIT();

        // QK: packed pairwise dots; keys (lane, lane+32) for 4 queries
        u64 s0p[4] = {0ull, 0ull, 0ull, 0ull}, s1p[4] = {0ull, 0ull, 0ull, 0ull};
#pragma unroll
        for (int d4 = 0; d4 < 16; d4++) {
            ulonglong2 k0 = *(const ulonglong2*)&Kb[lane][d4];
            ulonglong2 k1 = *(const ulonglong2*)&Kb[lane + 32][d4];
#pragma unroll
            for (int qq = 0; qq < 4; qq++) {
                ulonglong2 a = *(const ulonglong2*)&Qs[4 * w + qq][d4 * 4];
                s0p[qq] = ffma2(a.x, k0.x, s0p[qq]);
                s0p[qq] = ffma2(a.y, k0.y, s0p[qq]);
                s1p[qq] = ffma2(a.x, k1.x, s1p[qq]);
                s1p[qq] = ffma2(a.y, k1.y, s1p[qq]);
            }
        }
        float pv0[4], pv1[4];
#pragma unroll
        for (int qq = 0; qq < 4; qq++) {
            float2 t0 = unpack2(s0p[qq]);
            float2 t1 = unpack2(s1p[qq]);
            pv0[qq] = __expf((t0.x + t0.y) * 0.125f);
            pv1[qq] = __expf((t1.x + t1.y) * 0.125f);
            lsum[qq] += pv0[qq] + pv1[qq];
        }
        Ps[w][lane]      = make_float4(pv0[0], pv0[1], pv0[2], pv0[3]);
        Ps[w][lane + 32] = make_float4(pv1[0], pv1[1], pv1[2], pv1[3]);

        CP_WAIT0();
        __syncthreads();                      // V_t ready; done reading Kb

        // prefetch K_{t+1} (overlaps with PV)
        if (t < 3) {
            int nbase = kbase + 64;
            for (int i = tid; i < 1024; i += 160) {
                int s = i >> 4, c = i & 15;
                cp_async16(&Kb[s][c], &Kb4[(size_t)(nbase + s) * 16 + c]);
            }
            CP_COMMIT();
        }

        // PV: thread handles keys [sg*16,+16), dims [dg*4,+4) & [(dg+8)*4,+4)
#pragma unroll
        for (int i = 0; i < 16; i++) {
            int s = sg * 16 + i;
            float4 p  = Ps[w][s];
            ulonglong2 va = *(const ulonglong2*)&Vb[s][dg];
            ulonglong2 vb = *(const ulonglong2*)&Vb[s][dg + 8];
            u64 p2[4] = {pack2(p.x), pack2(p.y), pack2(p.z), pack2(p.w)};
#pragma unroll
            for (int qq = 0; qq < 4; qq++) {
                accp[qq][0] = ffma2(p2[qq], va.x, accp[qq][0]);
                accp[qq][1] = ffma2(p2[qq], va.y, accp[qq][1]);
                accp[qq][2] = ffma2(p2[qq], vb.x, accp[qq][2]);
                accp[qq][3] = ffma2(p2[qq], vb.y, accp[qq][3]);
            }
        }
    }

    // one-time reductions: lsum over 32 lanes; acc over the 4 sgroups
#pragma unroll
    for (int qq = 0; qq < 4; qq++) {
#pragma unroll
        for (int o = 16; o; o >>= 1)
            lsum[qq] += __shfl_xor_sync(0xffffffffu, lsum[qq], o);
#pragma unroll
        for (int j = 0; j < 4; j++) {
#pragma unroll
            for (int o = 8; o <= 16; o <<= 1) {
                u64 got = __shfl_xor_sync(0xffffffffu, accp[qq][j], o);
                accp[qq][j] = fadd2(accp[qq][j], got);
            }
        }
    }

    if (lane < 8) {
#pragma unroll
        for (int qq = 0; qq < 4; qq++) {
            int pa = (bh * NTOP + chunk * QCH + 4 * w + qq) * NSPLIT + split;
            ((ulonglong2*)g_acc)[pa * 16 + dg]     = make_ulonglong2(accp[qq][0], accp[qq][1]);
            ((ulonglong2*)g_acc)[pa * 16 + 8 + dg] = make_ulonglong2(accp[qq][2], accp[qq][3]);
        }
    }
    if (lane == 0) {
#pragma unroll
        for (int qq = 0; qq < 4; qq++) {
            int pa = (bh * NTOP + chunk * QCH + 4 * w + qq) * NSPLIT + split;
            g_am[pa] = 0.f; g_al[pa] = lsum[qq];
        }
    }
}

// ---------------------------------------------------------------------------
// Merge the 8 split partials per (bh, q) and write the output row.
// ---------------------------------------------------------------------------
__global__ void merge_kernel(float* __restrict__ out) {
    int w = (blockIdx.x * blockDim.x + threadIdx.x) >> 5;
    int lane = threadIdx.x & 31;
    if (w >= BH * NTOP) return;
    int bh = w / NTOP, qi = w % NTOP;
    int base = w * NSPLIT;

    float Lsum = 0.f, o0 = 0.f, o1 = 0.f;
#pragma unroll
    for (int s = 0; s < NSPLIT; s++) {
        Lsum += g_al[base + s];
        o0 += g_acc[(base + s) * D + lane];
        o1 += g_acc[(base + s) * D + lane + 32];
    }
    int row = g_top[bh * NTOP + qi];
    size_t orow = ((size_t)bh * L + row) * D;
    float inv = 1.0f / Lsum;
    out[orow + lane]      = o0 * inv;
    out[orow + lane + 32] = o1 * inv;
}

// ---------------------------------------------------------------------------
// Launch DAG (graph-captured fork-join):
//   main stream: compute_M -> topk -> attn -> [join] -> merge
//   side stream: sumv_part -> fill   (independent until merge)
// Streams/events are host objects (no device memory); created fresh per call
// and intentionally not destroyed (kernel_launch runs twice: correctness +
// capture; destroying a capture-participating stream would invalidate it).
// ---------------------------------------------------------------------------
extern "C" void kernel_launch(void* const* d_in, const int* in_sizes, int n_in,
                              void* d_out, int out_size) {
    const float* q = (const float*)d_in[0];
    const float* k = (const float*)d_in[1];
    const float* v = (const float*)d_in[2];
    float* out = (float*)d_out;

    cudaStream_t s1;
    cudaStreamCreateWithFlags(&s1, cudaStreamNonBlocking);
    cudaEvent_t e_fork, e_join;
    cudaEventCreateWithFlags(&e_fork, cudaEventDisableTiming);
    cudaEventCreateWithFlags(&e_join, cudaEventDisableTiming);

    // fork side stream off the (per-thread default) capture stream
    cudaEventRecord(e_fork, 0);
    cudaStreamWaitEvent(s1, e_fork, 0);
    sumv_part_kernel<<<BH * 8, 256, 0, s1>>>(v);
    fill_kernel<<<(B * H * L * D / 4) / 256, 256, 0, s1>>>((float4*)out);
    cudaEventRecord(e_join, s1);

    // main chain
    compute_M_kernel<<<BH * (L / 32), 256>>>(q, k);
    topk_kernel<<<BH, 1024>>>();
    attn_kernel<<<BH * 2 * NSPLIT, 160>>>(q, k, v);

    // join: merge overwrites top rows, so it must follow fill
    cudaStreamWaitEvent(0, e_join, 0);
    merge_kernel<<<(BH * NTOP * 32 + 255) / 256, 256>>>(out);
}